// round 2
// baseline (speedup 1.0000x reference)
#include <cuda_runtime.h>

// ---------------- scratch (no allocations allowed) ----------------
__device__ double g_sum_sq[3];   // per-level  sum( m^2 * (p-t)^2 )
__device__ double g_sum_m[3];    // per-level  sum( m )
__device__ float  g_mask0[16 * 80 * 80];
__device__ float  g_mask1[16 * 40 * 40];
__device__ float  g_mask2[16 * 20 * 20];

__global__ void init_kernel() {
    int i = threadIdx.x;
    if (i < 3) { g_sum_sq[i] = 0.0; g_sum_m[i] = 0.0; }
}

// ---------------- mask kernel ----------------
// blockIdx.y = image b; boxes of this image compacted into shared first.
template <int S>
__global__ void __launch_bounds__(256) mask_kernel(
    const float* __restrict__ bboxes, const int* __restrict__ bidx,
    int nbox, float* __restrict__ mout, int level)
{
    __shared__ int   cnt;
    __shared__ float s_xc[256], s_yc[256], s_iw[256], s_ih[256];
    __shared__ int   s_xl[256], s_xr[256], s_yt[256], s_yd[256];

    const int b = blockIdx.y;
    if (threadIdx.x == 0) cnt = 0;
    __syncthreads();

    for (int i = threadIdx.x; i < nbox; i += blockDim.x) {
        if (bidx[i] == b) {
            int xc = (int)floorf(bboxes[4 * i + 0] * (float)S);
            int yc = (int)floorf(bboxes[4 * i + 1] * (float)S);
            int w  = (int)floorf(bboxes[4 * i + 2] * (float)S);
            int h  = (int)floorf(bboxes[4 * i + 3] * (float)S);
            int xl = max(xc - w / 2, 0), xr = min(xc + w / 2, S - 1);
            int yt = max(yc - h / 2, 0), yd = min(yc + h / 2, S - 1);
            float wd = (float)(xr - xl + 1), ht = (float)(yd - yt + 1);
            int p = atomicAdd(&cnt, 1);
            s_xc[p] = (float)xc; s_yc[p] = (float)yc;
            // STD^2 * (width/2)^2 == width^2  (STD = 2)
            s_iw[p] = 1.0f / (wd * wd); s_ih[p] = 1.0f / (ht * ht);
            s_xl[p] = xl; s_xr[p] = xr; s_yt[p] = yt; s_yd[p] = yd;
        }
    }
    __syncthreads();
    const int n = cnt;

    const int pix = blockIdx.x * blockDim.x + threadIdx.x;
    float mval = 0.0f;
    if (pix < S * S) {
        const int y = pix / S, x = pix % S;
        const float fx = (float)x, fy = (float)y;
        for (int i = 0; i < n; i++) {
            if (x >= s_xl[i] && x <= s_xr[i] && y >= s_yt[i] && y <= s_yd[i]) {
                float dx = fx - s_xc[i], dy = fy - s_yc[i];
                float v = expf(-(dx * dx * s_iw[i] + dy * dy * s_ih[i]));
                mval = fmaxf(mval, v);
            }
        }
        mout[b * S * S + pix] = mval;
    }

    // block-reduce sum(m) -> g_sum_m[level]
    float v = mval;
    #pragma unroll
    for (int o = 16; o > 0; o >>= 1) v += __shfl_down_sync(0xffffffffu, v, o);
    __shared__ float ws[8];
    const int lane = threadIdx.x & 31, wid = threadIdx.x >> 5;
    if (lane == 0) ws[wid] = v;
    __syncthreads();
    if (wid == 0) {
        v = (lane < 8) ? ws[lane] : 0.0f;
        #pragma unroll
        for (int o = 4; o > 0; o >>= 1) v += __shfl_down_sync(0xffffffffu, v, o);
        if (lane == 0 && v != 0.0f) atomicAdd(&g_sum_m[level], (double)v);
    }
}

// ---------------- fused (p-t)^2 * m^2 reduction ----------------
template <int C, int S>
__global__ void __launch_bounds__(256) reduce_kernel(
    const float4* __restrict__ p, const float4* __restrict__ t,
    const float4* __restrict__ m, int level)
{
    const int HW4 = S * S / 4;
    const int N4  = 16 * C * HW4;
    float acc = 0.0f;
    const int stride = gridDim.x * blockDim.x;
    for (int i = blockIdx.x * blockDim.x + threadIdx.x; i < N4; i += stride) {
        float4 pv = p[i];
        float4 tv = t[i];
        int b   = i / (C * HW4);
        int pix = i % HW4;
        float4 mv = m[b * HW4 + pix];    // L2-resident
        float d0 = pv.x - tv.x, d1 = pv.y - tv.y;
        float d2 = pv.z - tv.z, d3 = pv.w - tv.w;
        acc += d0 * d0 * mv.x * mv.x + d1 * d1 * mv.y * mv.y
             + d2 * d2 * mv.z * mv.z + d3 * d3 * mv.w * mv.w;
    }

    // block reduce -> one double atomic per block
    #pragma unroll
    for (int o = 16; o > 0; o >>= 1) acc += __shfl_down_sync(0xffffffffu, acc, o);
    __shared__ float ws[8];
    const int lane = threadIdx.x & 31, wid = threadIdx.x >> 5;
    if (lane == 0) ws[wid] = acc;
    __syncthreads();
    if (wid == 0) {
        acc = (lane < 8) ? ws[lane] : 0.0f;
        #pragma unroll
        for (int o = 4; o > 0; o >>= 1) acc += __shfl_down_sync(0xffffffffu, acc, o);
        if (lane == 0 && acc != 0.0f) atomicAdd(&g_sum_sq[level], (double)acc);
    }
}

// ---------------- finalize ----------------
__global__ void finalize_kernel(float* __restrict__ out) {
    double total = g_sum_sq[0] / (128.0 * g_sum_m[0])
                 + g_sum_sq[1] / (256.0 * g_sum_m[1])
                 + g_sum_sq[2] / (512.0 * g_sum_m[2]);
    out[0] = (float)(total / 3.0);
}

extern "C" void kernel_launch(void* const* d_in, const int* in_sizes, int n_in,
                              void* d_out, int out_size)
{
    // metadata order is INTERLEAVED (setup_inputs loop inserts pred{i}, true{i}):
    const float* p0 = (const float*)d_in[0];   // y_pred0
    const float* t0 = (const float*)d_in[1];   // y_true0
    const float* p1 = (const float*)d_in[2];   // y_pred1
    const float* t1 = (const float*)d_in[3];   // y_true1
    const float* p2 = (const float*)d_in[4];   // y_pred2
    const float* t2 = (const float*)d_in[5];   // y_true2
    const float* bboxes = (const float*)d_in[6];
    // d_in[7] = cls (unused)
    const int* bidx = (const int*)d_in[8];
    const int nbox = in_sizes[8];
    float* out = (float*)d_out;

    float* m0; float* m1; float* m2;
    cudaGetSymbolAddress((void**)&m0, g_mask0);
    cudaGetSymbolAddress((void**)&m1, g_mask1);
    cudaGetSymbolAddress((void**)&m2, g_mask2);

    init_kernel<<<1, 32>>>();

    mask_kernel<80><<<dim3((80 * 80 + 255) / 256, 16), 256>>>(bboxes, bidx, nbox, m0, 0);
    mask_kernel<40><<<dim3((40 * 40 + 255) / 256, 16), 256>>>(bboxes, bidx, nbox, m1, 1);
    mask_kernel<20><<<dim3((20 * 20 + 255) / 256, 16), 256>>>(bboxes, bidx, nbox, m2, 2);

    const int RB = 148 * 8;   // grid-stride blocks per reduce
    reduce_kernel<128, 80><<<RB, 256>>>((const float4*)p0, (const float4*)t0, (const float4*)m0, 0);
    reduce_kernel<256, 40><<<RB, 256>>>((const float4*)p1, (const float4*)t1, (const float4*)m1, 1);
    reduce_kernel<512, 20><<<RB, 256>>>((const float4*)p2, (const float4*)t2, (const float4*)m2, 2);

    finalize_kernel<<<1, 1>>>(out);
}

// round 3
// speedup vs baseline: 1.1529x; 1.1529x over previous
#include <cuda_runtime.h>

// ---------------- static grid geometry ----------------
// mask kernel: level0 = 16*25 = 400 blocks, level1 = 16*7 = 112, level2 = 16*2 = 32
#define MB0 400
#define MB1 112
#define MB2 32
#define MB_TOT (MB0 + MB1 + MB2)          // 544
// reduce kernel: work ratio 4:2:1
#define RB0 677
#define RB1 338
#define RB2 169
#define RB_TOT (RB0 + RB1 + RB2)          // 1184

// ---------------- scratch (no allocations allowed) ----------------
__device__ double g_part_m[MB_TOT];       // per-block sum(m), slot = blockIdx.x
__device__ double g_part_sq[RB_TOT];      // per-block sum(m^2*(p-t)^2)
__device__ float  g_mask0[16 * 80 * 80];
__device__ float  g_mask1[16 * 40 * 40];
__device__ float  g_mask2[16 * 20 * 20];

// ---------------- block reduce helper (float -> one value in thread 0) ----------------
__device__ __forceinline__ float block_reduce(float v) {
    #pragma unroll
    for (int o = 16; o > 0; o >>= 1) v += __shfl_down_sync(0xffffffffu, v, o);
    __shared__ float ws[8];
    const int lane = threadIdx.x & 31, wid = threadIdx.x >> 5;
    if (lane == 0) ws[wid] = v;
    __syncthreads();
    if (wid == 0) {
        v = (lane < (int)(blockDim.x >> 5)) ? ws[lane] : 0.0f;
        #pragma unroll
        for (int o = 4; o > 0; o >>= 1) v += __shfl_down_sync(0xffffffffu, v, o);
    }
    return v;   // valid in thread 0
}

// ---------------- fused mask kernel: all 3 levels ----------------
template <int S>
__device__ __forceinline__ void mask_work(
    const float* __restrict__ bboxes, const int* __restrict__ bidx,
    int nbox, float* __restrict__ mout, int b, int pixblk)
{
    __shared__ int   cnt;
    __shared__ float s_xc[256], s_yc[256], s_iw[256], s_ih[256];
    __shared__ int   s_xl[256], s_xr[256], s_yt[256], s_yd[256];

    if (threadIdx.x == 0) cnt = 0;
    __syncthreads();

    for (int i = threadIdx.x; i < nbox; i += blockDim.x) {
        if (bidx[i] == b) {
            int xc = (int)floorf(bboxes[4 * i + 0] * (float)S);
            int yc = (int)floorf(bboxes[4 * i + 1] * (float)S);
            int w  = (int)floorf(bboxes[4 * i + 2] * (float)S);
            int h  = (int)floorf(bboxes[4 * i + 3] * (float)S);
            int xl = max(xc - w / 2, 0), xr = min(xc + w / 2, S - 1);
            int yt = max(yc - h / 2, 0), yd = min(yc + h / 2, S - 1);
            float wd = (float)(xr - xl + 1), ht = (float)(yd - yt + 1);
            int p = atomicAdd(&cnt, 1);
            s_xc[p] = (float)xc; s_yc[p] = (float)yc;
            // STD^2 * (width/2)^2 == width^2  (STD = 2)
            s_iw[p] = 1.0f / (wd * wd); s_ih[p] = 1.0f / (ht * ht);
            s_xl[p] = xl; s_xr[p] = xr; s_yt[p] = yt; s_yd[p] = yd;
        }
    }
    __syncthreads();
    const int n = cnt;

    const int pix = pixblk * 256 + threadIdx.x;
    float mval = 0.0f;
    if (pix < S * S) {
        const int y = pix / S, x = pix % S;
        const float fx = (float)x, fy = (float)y;
        for (int i = 0; i < n; i++) {
            if (x >= s_xl[i] && x <= s_xr[i] && y >= s_yt[i] && y <= s_yd[i]) {
                float dx = fx - s_xc[i], dy = fy - s_yc[i];
                float v = expf(-(dx * dx * s_iw[i] + dy * dy * s_ih[i]));
                mval = fmaxf(mval, v);
            }
        }
        mout[b * S * S + pix] = mval;
    }

    float v = block_reduce(mval);
    if (threadIdx.x == 0) g_part_m[blockIdx.x] = (double)v;
}

__global__ void __launch_bounds__(256) mask_fused_kernel(
    const float* __restrict__ bboxes, const int* __restrict__ bidx, int nbox)
{
    const int blk = blockIdx.x;
    if (blk < MB0) {
        mask_work<80>(bboxes, bidx, nbox, g_mask0, blk / 25, blk % 25);
    } else if (blk < MB0 + MB1) {
        const int l = blk - MB0;
        mask_work<40>(bboxes, bidx, nbox, g_mask1, l / 7, l % 7);
    } else {
        const int l = blk - (MB0 + MB1);
        mask_work<20>(bboxes, bidx, nbox, g_mask2, l / 2, l % 2);
    }
}

// ---------------- fused reduce kernel: all 3 levels ----------------
template <int C, int S>
__device__ __forceinline__ void reduce_work(
    const float4* __restrict__ p, const float4* __restrict__ t,
    const float4* __restrict__ m, int blk_local, int nblk)
{
    const int HW4 = S * S / 4;
    const int N4  = 16 * C * HW4;
    float acc = 0.0f;
    const int stride = nblk * 256;
    for (int i = blk_local * 256 + threadIdx.x; i < N4; i += stride) {
        float4 pv = p[i];
        float4 tv = t[i];
        int b   = i / (C * HW4);
        int pix = i % HW4;
        float4 mv = m[b * HW4 + pix];    // L2-resident
        float d0 = pv.x - tv.x, d1 = pv.y - tv.y;
        float d2 = pv.z - tv.z, d3 = pv.w - tv.w;
        acc += d0 * d0 * mv.x * mv.x + d1 * d1 * mv.y * mv.y
             + d2 * d2 * mv.z * mv.z + d3 * d3 * mv.w * mv.w;
    }
    float v = block_reduce(acc);
    if (threadIdx.x == 0) g_part_sq[blockIdx.x] = (double)v;
}

__global__ void __launch_bounds__(256) reduce_fused_kernel(
    const float4* __restrict__ p0, const float4* __restrict__ t0,
    const float4* __restrict__ p1, const float4* __restrict__ t1,
    const float4* __restrict__ p2, const float4* __restrict__ t2)
{
    const int blk = blockIdx.x;
    if (blk < RB0) {
        reduce_work<128, 80>(p0, t0, (const float4*)g_mask0, blk, RB0);
    } else if (blk < RB0 + RB1) {
        reduce_work<256, 40>(p1, t1, (const float4*)g_mask1, blk - RB0, RB1);
    } else {
        reduce_work<512, 20>(p2, t2, (const float4*)g_mask2, blk - (RB0 + RB1), RB2);
    }
}

// ---------------- finalize: sum partials, emit loss ----------------
__device__ __forceinline__ double sum_range(const double* a, int lo, int hi) {
    double s = 0.0;
    for (int i = lo + threadIdx.x; i < hi; i += blockDim.x) s += a[i];
    __shared__ double sd[256];
    sd[threadIdx.x] = s;
    __syncthreads();
    for (int o = 128; o > 0; o >>= 1) {
        if (threadIdx.x < o) sd[threadIdx.x] += sd[threadIdx.x + o];
        __syncthreads();
    }
    double r = sd[0];
    __syncthreads();
    return r;
}

__global__ void __launch_bounds__(256) finalize_kernel(float* __restrict__ out) {
    double m0 = sum_range(g_part_m, 0, MB0);
    double m1 = sum_range(g_part_m, MB0, MB0 + MB1);
    double m2 = sum_range(g_part_m, MB0 + MB1, MB_TOT);
    double q0 = sum_range(g_part_sq, 0, RB0);
    double q1 = sum_range(g_part_sq, RB0, RB0 + RB1);
    double q2 = sum_range(g_part_sq, RB0 + RB1, RB_TOT);
    if (threadIdx.x == 0) {
        double total = q0 / (128.0 * m0) + q1 / (256.0 * m1) + q2 / (512.0 * m2);
        out[0] = (float)(total / 3.0);
    }
}

extern "C" void kernel_launch(void* const* d_in, const int* in_sizes, int n_in,
                              void* d_out, int out_size)
{
    // metadata order is INTERLEAVED: pred0, true0, pred1, true1, pred2, true2
    const float* p0 = (const float*)d_in[0];
    const float* t0 = (const float*)d_in[1];
    const float* p1 = (const float*)d_in[2];
    const float* t1 = (const float*)d_in[3];
    const float* p2 = (const float*)d_in[4];
    const float* t2 = (const float*)d_in[5];
    const float* bboxes = (const float*)d_in[6];
    // d_in[7] = cls (unused)
    const int* bidx = (const int*)d_in[8];
    const int nbox = in_sizes[8];
    float* out = (float*)d_out;

    mask_fused_kernel<<<MB_TOT, 256>>>(bboxes, bidx, nbox);

    reduce_fused_kernel<<<RB_TOT, 256>>>(
        (const float4*)p0, (const float4*)t0,
        (const float4*)p1, (const float4*)t1,
        (const float4*)p2, (const float4*)t2);

    finalize_kernel<<<1, 256>>>(out);
}